// round 3
// baseline (speedup 1.0000x reference)
#include <cuda_runtime.h>
#include <cstdint>

// FMFMNeuronInhib: T=4096 steps, B=4096 neurons.
// Input  x: [T][B][2] float32
// Output: spk[T*B] | exc[T*B] | inh[T*B] | mem[T*B]  (concatenated, float32)
//
// Warp-specialized design, 128 blocks x 160 threads (5 warps), 32 neurons/block:
//   w0: nonlinear mem recurrence (critical chain), writes mem to smem ring
//   w1: smem -> mem_rec
//   w2: smem -> spk_rec
//   w3: inh recurrence + inh_rec   (free-running)
//   w4: exc map + exc_rec          (free-running, doubles as L2 prefetcher for w0)

#define T_STEPS 4096
#define B_NEUR  4096
#define CH      128            // steps per smem chunk
#define NCHUNK  (T_STEPS / CH)

__global__ __launch_bounds__(160, 1)
void fmfm_kernel(const float* __restrict__ x,
                 const float* __restrict__ w_exc,
                 const float* __restrict__ w_inh_p,
                 float* __restrict__ out)
{
    __shared__ float smem_mem[2][CH][32];   // 32 KB

    const int lane = threadIdx.x & 31;
    const int wid  = threadIdx.x >> 5;
    const int b    = blockIdx.x * 32 + lane;

    const float w00  = w_exc[0];
    const float w01  = w_exc[1];
    const float winh = *w_inh_p;

    float* __restrict__ O_spk = out;
    float* __restrict__ O_exc = out + (size_t)T_STEPS * B_NEUR;
    float* __restrict__ O_inh = out + 2ull * T_STEPS * B_NEUR;
    float* __restrict__ O_mem = out + 3ull * T_STEPS * B_NEUR;

    // per-neuron input stream: float2 per step, stride B_NEUR float2s
    const float2* __restrict__ xp = reinterpret_cast<const float2*>(x) + b;

    if (wid == 0) {
        // ---------------- compute warp: mem chain ----------------
        float mem = 0.0f, inh = 0.0f;

        // 4 prefetch groups of 8 steps (32 steps ahead)
        float2 pre[4][8];
        #pragma unroll
        for (int g = 0; g < 4; g++)
            #pragma unroll
            for (int i = 0; i < 8; i++)
                pre[g][i] = xp[(size_t)(g * 8 + i) * B_NEUR];

        int t = 0;
        for (int c = 0; c < NCHUNK; c++) {
            const int p = c & 1;
            for (int g4 = 0; g4 < CH; g4 += 32) {
                #pragma unroll
                for (int j = 0; j < 4; j++) {
                    // consume pre[j] = steps t .. t+7
                    #pragma unroll
                    for (int i = 0; i < 8; i++) {
                        const float x0 = pre[j][i].x;
                        const float x1 = pre[j][i].y;
                        inh = __fmaf_rn(0.6f, inh, x0);                 // beta_inh*inh + x0
                        float cur = __fmaf_rn(x1, w01, __fmul_rn(x0, w00)); // x0*w00 + x1*w01
                        cur = __fmaf_rn(winh, inh, cur);                // + w_inh*inh (==+0 here)
                        const float reset = (mem > 1.0f) ? 1.0f : 0.0f; // spike(mem - 1)
                        const float m2 = __fadd_rn(__fmul_rn(0.9f, mem), cur);
                        mem = __fsub_rn(m2, reset);                     // ((0.9*m)+cur)-reset
                        smem_mem[p][g4 + j * 8 + i][lane] = mem;
                    }
                    // reload pre[j] with steps t+32 .. t+39
                    const int tl = t + 32;
                    if (tl < T_STEPS) {
                        #pragma unroll
                        for (int i = 0; i < 8; i++)
                            pre[j][i] = xp[(size_t)(tl + i) * B_NEUR];
                    }
                    t += 8;
                }
            }
            asm volatile("bar.sync 1, 96;" ::: "memory");
        }
    } else if (wid == 1) {
        // ---------------- mem writer ----------------
        for (int c = 0; c < NCHUNK; c++) {
            asm volatile("bar.sync 1, 96;" ::: "memory");
            const int p = c & 1;
            float* __restrict__ dst = O_mem + (size_t)c * CH * B_NEUR + b;
            #pragma unroll 8
            for (int tt = 0; tt < CH; tt++)
                dst[(size_t)tt * B_NEUR] = smem_mem[p][tt][lane];
        }
    } else if (wid == 2) {
        // ---------------- spk writer ----------------
        for (int c = 0; c < NCHUNK; c++) {
            asm volatile("bar.sync 1, 96;" ::: "memory");
            const int p = c & 1;
            float* __restrict__ dst = O_spk + (size_t)c * CH * B_NEUR + b;
            #pragma unroll 8
            for (int tt = 0; tt < CH; tt++) {
                const float m = smem_mem[p][tt][lane];
                dst[(size_t)tt * B_NEUR] = (__fsub_rn(m, 1.0f) > 0.0f) ? 1.0f : 0.0f;
            }
        }
    } else if (wid == 3) {
        // ---------------- inh chain + writer (free-running) ----------------
        float inh = 0.0f;
        for (int t0 = 0; t0 < T_STEPS; t0 += 16) {
            float2 xv[16];
            #pragma unroll
            for (int i = 0; i < 16; i++)
                xv[i] = xp[(size_t)(t0 + i) * B_NEUR];
            #pragma unroll
            for (int i = 0; i < 16; i++) {
                inh = __fmaf_rn(0.6f, inh, xv[i].x);
                O_inh[(size_t)(t0 + i) * B_NEUR + b] = __fmul_rn(winh, inh);
            }
        }
    } else {
        // ---------------- exc writer (free-running, prefetches stream into L2) ----------------
        for (int t0 = 0; t0 < T_STEPS; t0 += 16) {
            float2 xv[16];
            #pragma unroll
            for (int i = 0; i < 16; i++)
                xv[i] = xp[(size_t)(t0 + i) * B_NEUR];
            #pragma unroll
            for (int i = 0; i < 16; i++) {
                const float e = __fmaf_rn(xv[i].y, w01, __fmul_rn(xv[i].x, w00));
                O_exc[(size_t)(t0 + i) * B_NEUR + b] = e;
            }
        }
    }
}

extern "C" void kernel_launch(void* const* d_in, const int* in_sizes, int n_in,
                              void* d_out, int out_size)
{
    const float* x      = (const float*)d_in[0];
    const float* w_exc  = (const float*)d_in[1];
    const float* w_inh  = (const float*)d_in[2];
    float* out          = (float*)d_out;
    (void)in_sizes; (void)n_in; (void)out_size;

    fmfm_kernel<<<B_NEUR / 32, 160>>>(x, w_exc, w_inh, out);
}